// round 15
// baseline (speedup 1.0000x reference)
#include <cuda_runtime.h>
#include <cuda_bf16.h>
#include <cuda_fp16.h>
#include <math.h>
#include <stdint.h>

// Problem dims
#define BB 256
#define NN 77
#define DD 768
#define KK 16
#define DN 768
#define HID 512
#define MTOT (BB*KK)          // 4096
#define SCALE 0.10206207261596575f   // (768/8)^-0.5
#define KH 768                // GEMM K (fp16)
#define KCH 24                // 768/32 chunks
#define MSC (BB*NN)           // 19712 score rows = 308*64

// ---------------- scratch (device globals; no allocation) ----------------
__device__ float g_Qp[16][KK*DN];
__device__ float g_Q[KK*DN];
__device__ float g_c[KK];
__device__ float g_Sc[(size_t)MSC*KK];   // raw scores [m][k]
__device__ float g_Ep[2][BB*256];        // partial edge logits
__device__ float g_V[MTOT*DN];
__device__ float g_rowsum[MTOT];
__device__ float g_H[MTOT*2*HID];
__device__ float g_M[MTOT*DN];
// fp16 operand buffers (uint4 for 16B alignment)
__device__ uint4 g_wh [(size_t)MSC*DD/8];     // fp16 copy of w (by kScoreG)
__device__ uint4 g_Pth[KK*DN/8];              // fp16 P, node-major [16][768]
__device__ uint4 g_Abf [(size_t)MTOT*KH/8];   // fp16 U
__device__ uint4 g_Abf2[(size_t)MTOT*KH/8];   // fp16 V
__device__ uint4 g_WbfV [768*KH/8];
__device__ uint4 g_WbfG0[768*KH/8];
__device__ uint4 g_WbfG1[768*KH/8];
__device__ uint4 g_WbfE1[1024*KH/8];

__device__ __forceinline__ uint32_t smem_u32(const void* p) {
    uint32_t a;
    asm("{ .reg .u64 t; cvta.to.shared.u64 t, %1; cvt.u32.u64 %0, t; }"
        : "=r"(a) : "l"(p));
    return a;
}

__device__ __forceinline__ unsigned packh2(float a, float b) {
    __half2 h = __floats2half2_rn(a, b);
    return *(unsigned*)&h;
}

// ---------------- kPrep: weight conversions + kQ partials -----------------
// blocks [0,1248): kSplitAllW ; [1248,1296): kQ
#define PREP_SPLIT 1248
#define PREP_KQ 48
__global__ void kPrep(const float* __restrict__ Wv,
                      const float* __restrict__ Wg,
                      const float* __restrict__ We1,
                      const float* __restrict__ nq,
                      const float* __restrict__ Wq) {
    int bid = blockIdx.x;
    int tid = threadIdx.x;
    if (bid < PREP_SPLIT) {
        int sid = bid * 256 + tid;
        float a[8];
        __half* out;
        int e0;
        if (sid < 221184) {
            int job = sid / 73728, s = sid % 73728;
            int n = s % 768, seg = s / 768;
            e0 = seg * 8;
            const float* Wp = (job == 0) ? Wv : (job == 1) ? Wg : (Wg + 768 * 768);
            uint4* o4 = (job == 0) ? g_WbfV : (job == 1) ? g_WbfG0 : g_WbfG1;
            out = (__half*)o4 + (size_t)n * KH;
            #pragma unroll
            for (int i = 0; i < 8; i++) a[i] = Wp[(size_t)(e0 + i) * 768 + n];
        } else {
            int s = sid - 221184;
            int n = s % 1024, seg = s / 1024;
            e0 = seg * 8;
            out = (__half*)g_WbfE1 + (size_t)n * KH;
            size_t base = (n < HID) ? (size_t)n : ((size_t)768 * HID + (n - HID));
            #pragma unroll
            for (int i = 0; i < 8; i++) a[i] = We1[base + (size_t)(e0 + i) * HID];
        }
        unsigned h[4];
        #pragma unroll
        for (int i = 0; i < 4; i++) h[i] = packh2(a[2 * i], a[2 * i + 1]);
        *(uint4*)(out + e0) = *(uint4*)h;
    } else {
        int q = bid - PREP_SPLIT;
        int dblk = q % 3, sl = q / 3;
        int d = dblk * 256 + tid;
        int e0 = sl * 48;
        __shared__ float snq[KK][48];
        for (int idx = tid; idx < KK * 48; idx += 256)
            snq[idx / 48][idx % 48] = nq[(idx / 48) * DN + e0 + idx % 48];
        __syncthreads();
        float acc[KK];
        #pragma unroll
        for (int k = 0; k < KK; k++) acc[k] = 0.f;
        const float* wp = Wq + (size_t)e0 * DN + d;
        #pragma unroll 4
        for (int e = 0; e < 48; e++) {
            float wv = wp[(size_t)e * DN];
            #pragma unroll
            for (int k = 0; k < KK; k++) acc[k] += snq[k][e] * wv;
        }
        #pragma unroll
        for (int k = 0; k < KK; k++) g_Qp[sl][k * DN + d] = acc[k];
    }
}

// ---------------- kQr: sum 16 partials + bq -> g_Q ------------------------
__global__ void kQr(const float* __restrict__ bq) {
    int i = blockIdx.x * 256 + threadIdx.x;   // 12288
    float s = bq[i % DN];
    #pragma unroll
    for (int sl = 0; sl < 16; sl++) s += g_Qp[sl][i];
    g_Q[i] = s;
}

// ---------------- kP: P -> fp16 g_Pth directly; c[k] ----------------------
__global__ void kP(const float* __restrict__ Wk, const float* __restrict__ bk) {
    __shared__ float sQ[KK][DN];   // 48 KB
    __shared__ float sPo[8][17];
    int tid = threadIdx.x;
    int lane = tid & 31, warp = tid >> 5;
    for (int idx = tid; idx < KK * DN; idx += 256)
        sQ[idx / DN][idx % DN] = g_Q[idx];
    __syncthreads();

    int j = blockIdx.x * 8 + warp;
    const float4* wr = (const float4*)(Wk + (size_t)j * DN);
    float acc[KK];
    #pragma unroll
    for (int k = 0; k < KK; k++) acc[k] = 0.f;
    #pragma unroll
    for (int it = 0; it < 6; it++) {
        int e = it * 128 + lane * 4;
        float4 wv = wr[it * 32 + lane];
        #pragma unroll
        for (int k = 0; k < KK; k++) {
            float4 qv = *(const float4*)&sQ[k][e];
            acc[k] += wv.x * qv.x + wv.y * qv.y + wv.z * qv.z + wv.w * qv.w;
        }
    }
    float out = 0.f;
    #pragma unroll
    for (int k = 0; k < KK; k++) {
        float v = acc[k];
        v += __shfl_xor_sync(0xFFFFFFFFu, v, 16);
        v += __shfl_xor_sync(0xFFFFFFFFu, v, 8);
        v += __shfl_xor_sync(0xFFFFFFFFu, v, 4);
        v += __shfl_xor_sync(0xFFFFFFFFu, v, 2);
        v += __shfl_xor_sync(0xFFFFFFFFu, v, 1);
        if (lane == k) out = v;
    }
    if (lane < KK) sPo[warp][lane] = out;   // sPo[jj][k]
    __syncthreads();
    if (tid < 128) {
        int k = tid >> 3, jj = tid & 7;
        ((__half*)g_Pth)[k * DN + blockIdx.x * 8 + jj] = __float2half_rn(sPo[jj][k]);
    }

    if (blockIdx.x >= 94) {
        int k = (blockIdx.x - 94) * 8 + warp;
        float cc = 0.f;
        #pragma unroll
        for (int it = 0; it < 6; it++) {
            int e = it * 128 + lane * 4;
            float4 bv = *(const float4*)(bk + e);
            float4 qv = *(const float4*)&sQ[k][e];
            cc += bv.x * qv.x + bv.y * qv.y + bv.z * qv.z + bv.w * qv.w;
        }
        cc += __shfl_xor_sync(0xFFFFFFFFu, cc, 16);
        cc += __shfl_xor_sync(0xFFFFFFFFu, cc, 8);
        cc += __shfl_xor_sync(0xFFFFFFFFu, cc, 4);
        cc += __shfl_xor_sync(0xFFFFFFFFu, cc, 2);
        cc += __shfl_xor_sync(0xFFFFFFFFu, cc, 1);
        if (lane == 0) g_c[k] = cc;
    }
}

// ---------------- kScoreG: fused w->fp16 + scores GEMM --------------------
// grid 308, 64-row tiles. Reads fp32 w, converts in regs, stores fp16 to
// smem (reg-double-buffered) AND to g_wh. Warps 0-3 do mma (tile 64x16).
__global__ __launch_bounds__(256) void kScoreG(const float* __restrict__ w) {
    __shared__ __align__(1024) __half sB[16 * 768];   // 24 KB
    __shared__ __align__(1024) __half sA[2][64 * 32]; // 8 KB

    const int m0 = blockIdx.x * 64;
    const int tid = threadIdx.x;
    const int lane = tid & 31, warp = tid >> 5;
    const uint32_t sAu = smem_u32(sA), sBu = smem_u32(sB);

    // load B (16 nodes x 768 fp16) with unit-XOR swizzle
    for (int idx = tid; idx < 16 * 96; idx += 256) {
        int r = idx / 96, u = idx % 96;
        uint4 v = g_Pth[r * 96 + u];
        *(uint4*)((char*)sB + r * 1536 + ((u ^ (r & 7)) << 4)) = v;
    }

    // A slots: 2 per thread; slot = (row, q) with q = 4-col group (0..7)
    uint32_t soff[2];
    const float* gw[2];
    __half* ghw[2];
    #pragma unroll
    for (int i = 0; i < 2; i++) {
        int u = tid * 2 + i, row = u >> 3, q = u & 7;
        int quad = q >> 1;
        soff[i] = row * 64 + ((quad ^ ((row >> 1) & 3)) << 4) + (q & 1) * 8;
        gw[i]  = w + (size_t)(m0 + row) * DD + q * 4;
        ghw[i] = (__half*)g_wh + (size_t)(m0 + row) * DD + q * 4;
    }

    // ldmatrix offsets for warps 0-3 (rows warp*16 + r16)
    const int r16 = lane & 15, hh = lane >> 4;
    uint32_t aoff[2];
    #pragma unroll
    for (int s = 0; s < 2; s++) {
        int quad = 2 * s + hh;
        int row = warp * 16 + r16;   // valid for warp<4
        aoff[s] = row * 64 + ((quad ^ ((row >> 1) & 3)) << 4);
    }

    float acc[2][4];
    #pragma unroll
    for (int b = 0; b < 2; b++)
        #pragma unroll
        for (int r = 0; r < 4; r++) acc[b][r] = 0.f;

    float4 ra[2];
    #pragma unroll
    for (int i = 0; i < 2; i++) ra[i] = *(const float4*)gw[i];

    for (int c = 0; c < KCH; c++) {
        const int buf = c & 1;
        // convert + store (smem & g_wh)
        #pragma unroll
        for (int i = 0; i < 2; i++) {
            uint2 hv;
            hv.x = packh2(ra[i].x, ra[i].y);
            hv.y = packh2(ra[i].z, ra[i].w);
            *(uint2*)((char*)sA + buf * 4096 + soff[i]) = hv;
            *(uint2*)(ghw[i] + c * 32) = hv;
        }
        __syncthreads();
        if (c + 1 < KCH) {
            #pragma unroll
            for (int i = 0; i < 2; i++)
                ra[i] = *(const float4*)(gw[i] + (c + 1) * 32);
        }
        if (warp < 4) {
            #pragma unroll
            for (int s = 0; s < 2; s++) {
                uint32_t afr[4];
                asm volatile("ldmatrix.sync.aligned.m8n8.x4.shared.b16 "
                             "{%0,%1,%2,%3}, [%4];"
                             : "=r"(afr[0]), "=r"(afr[1]), "=r"(afr[2]), "=r"(afr[3])
                             : "r"(sAu + buf * 4096 + aoff[s]));
                int u = c * 4 + s * 2 + hh;
                uint32_t baddr = sBu + r16 * 1536 + ((u ^ (r16 & 7)) << 4);
                uint32_t r0, r1, r2, r3;
                asm volatile("ldmatrix.sync.aligned.m8n8.x4.shared.b16 "
                             "{%0,%1,%2,%3}, [%4];"
                             : "=r"(r0), "=r"(r1), "=r"(r2), "=r"(r3) : "r"(baddr));
                uint32_t bfr[2][2];
                bfr[0][0] = r0; bfr[0][1] = r2;
                bfr[1][0] = r1; bfr[1][1] = r3;
                #pragma unroll
                for (int nt = 0; nt < 2; nt++) {
                    asm volatile(
                        "mma.sync.aligned.m16n8k16.row.col.f32.f16.f16.f32 "
                        "{%0,%1,%2,%3}, {%4,%5,%6,%7}, {%8,%9}, {%0,%1,%2,%3};"
                        : "+f"(acc[nt][0]), "+f"(acc[nt][1]),
                          "+f"(acc[nt][2]), "+f"(acc[nt][3])
                        : "r"(afr[0]), "r"(afr[1]), "r"(afr[2]), "r"(afr[3]),
                          "r"(bfr[nt][0]), "r"(bfr[nt][1]));
                }
            }
        }
        __syncthreads();
    }

    if (warp < 4) {
        #pragma unroll
        for (int half = 0; half < 2; half++) {
            int row = m0 + warp * 16 + (lane >> 2) + 8 * half;
            float* crow = g_Sc + (size_t)row * KK;
            #pragma unroll
            for (int nt = 0; nt < 2; nt++) {
                int col = nt * 8 + (lane & 3) * 2;
                crow[col]     = acc[nt][half * 2 + 0];
                crow[col + 1] = acc[nt][half * 2 + 1];
            }
        }
    }
}

// ---------------- kU: softmax (from g_Sc) + U = S^T w, fp16 U out ---------
// grid (BB, 4), 96 threads; dh==0 also writes outS + rowsum
__global__ void kU(const int* __restrict__ mask, float* __restrict__ outS) {
    int b = blockIdx.x, dh = blockIdx.y;
    int tid = threadIdx.x;
    int d0 = dh * 192 + tid * 2;
    __shared__ float sS[NN * KK];
    __shared__ float sC[KK];
    if (tid < KK) sC[tid] = g_c[tid];
    __syncthreads();
    if (tid < NN) {
        int n = tid;
        float v[KK];
        const float4* src = (const float4*)(g_Sc + (size_t)(b * NN + n) * KK);
        #pragma unroll
        for (int q = 0; q < 4; q++) *(float4*)&v[q * 4] = src[q];
        if (mask[b * NN + n] == 0) {
            #pragma unroll
            for (int k = 0; k < KK; k++) sS[n * KK + k] = 1.0f / 16.0f;
        } else {
            float sc[KK]; float m = -3.4e38f;
            #pragma unroll
            for (int k = 0; k < KK; k++) { sc[k] = (v[k] + sC[k]) * SCALE; m = fmaxf(m, sc[k]); }
            float e[KK]; float s = 0.f;
            #pragma unroll
            for (int k = 0; k < KK; k++) { e[k] = __expf(sc[k] - m); s += e[k]; }
            float inv = 1.0f / s;
            #pragma unroll
            for (int k = 0; k < KK; k++) sS[n * KK + k] = e[k] * inv;
        }
        if (dh == 0) {
            float4* dst = (float4*)(outS + (size_t)(b * NN + n) * KK);
            #pragma unroll
            for (int q = 0; q < 4; q++) dst[q] = *(float4*)&sS[n * KK + q * 4];
        }
    }
    __syncthreads();
    if (dh == 0 && tid < KK) {
        float s = 0.f;
        for (int n = 0; n < NN; n++) s += sS[n * KK + tid];
        g_rowsum[b * KK + tid] = s;
    }

    float2 acc[KK];
    #pragma unroll
    for (int k = 0; k < KK; k++) { acc[k].x = 0.f; acc[k].y = 0.f; }
    const __half* wp = (const __half*)g_wh + (size_t)b * NN * DD + d0;
    #pragma unroll 4
    for (int n = 0; n < NN; n++) {
        __half2 hv = *(const __half2*)(wp + (size_t)n * DD);
        float2 wv = __half22float2(hv);
        const float* srow = sS + n * KK;
        #pragma unroll
        for (int k = 0; k < KK; k++) {
            float s = srow[k];
            acc[k].x += s * wv.x; acc[k].y += s * wv.y;
        }
    }
    #pragma unroll
    for (int k = 0; k < KK; k++) {
        __half* ur = (__half*)g_Abf + (size_t)(b * KK + k) * KH;
        *(unsigned*)(ur + d0) = packh2(acc[k].x, acc[k].y);
    }
}

// ---------------- kTGemm: mma.sync fp16 GEMM ------------------------------
__global__ __launch_bounds__(256, 2) void kTGemm(
    int asel, int wsel, int mode, const float* __restrict__ bias,
    const float* __restrict__ nq, const float* __restrict__ gatep)
{
    __shared__ __align__(1024) __half sA[3][128 * 32];
    __shared__ __align__(1024) __half sB[3][128 * 32];

    const __half* Ag = (const __half*)(asel ? g_Abf2 : g_Abf);
    const int m0 = blockIdx.x * 128;
    int n0 = blockIdx.y * 128;
    const __half* Bg;
    float* C; int Ncols; int emode = mode;
    if (mode == 3) {
        if (blockIdx.y < 8) {
            Bg = (const __half*)g_WbfE1; C = g_H; Ncols = 2 * HID; emode = 0;
        } else {
            n0 = (blockIdx.y - 8) * 128;
            Bg = (const __half*)g_WbfG0; C = g_M; Ncols = DN; emode = 2;
        }
    } else {
        const uint4* B4 = (wsel == 0) ? g_WbfV : (wsel == 1) ? g_WbfG0
                        : (wsel == 2) ? g_WbfG1 : g_WbfE1;
        Bg = (const __half*)B4;
        if (mode == 0)      { C = g_H; Ncols = 2 * HID; }
        else if (mode == 1) { C = g_V; Ncols = DN; }
        else                { C = g_M; Ncols = DN; }
    }

    const int tid = threadIdx.x;
    const int lane = tid & 31, warp = tid >> 5;
    const int wm = warp >> 1, wn = warp & 1;

    const uint32_t sAu = smem_u32(sA), sBu = smem_u32(sB);

    uint32_t soff[2];
    const __half* gA[2];
    const __half* gB[2];
    #pragma unroll
    for (int i = 0; i < 2; i++) {
        int v = tid * 2 + i, row = v >> 2, q = v & 3;
        soff[i] = row * 64 + ((q ^ ((row >> 1) & 3)) << 4);
        gA[i] = Ag + (size_t)(m0 + row) * KH + q * 8;
        gB[i] = Bg + (size_t)(n0 + row) * KH + q * 8;
    }

    const int r16 = lane & 15, hh = lane >> 4;
    uint32_t aoff[2][2], boff[2][4];
    #pragma unroll
    for (int s = 0; s < 2; s++) {
        int quad = 2 * s + hh;
        #pragma unroll
        for (int mt = 0; mt < 2; mt++) {
            int row = wm * 32 + mt * 16 + r16;
            aoff[s][mt] = row * 64 + ((quad ^ ((row >> 1) & 3)) << 4);
        }
        #pragma unroll
        for (int nb = 0; nb < 4; nb++) {
            int row = wn * 64 + nb * 16 + r16;
            boff[s][nb] = row * 64 + ((quad ^ ((row >> 1) & 3)) << 4);
        }
    }

    float acc[2][8][4];
    #pragma unroll
    for (int a = 0; a < 2; a++)
        #pragma unroll
        for (int b = 0; b < 8; b++)
            #pragma unroll
            for (int r = 0; r < 4; r++) acc[a][b][r] = 0.f;

    #pragma unroll
    for (int st = 0; st < 2; st++) {
        uint32_t da = sAu + st * 8192, db = sBu + st * 8192;
        #pragma unroll
        for (int i = 0; i < 2; i++) {
            asm volatile("cp.async.ca.shared.global [%0], [%1], 16;"
                         :: "r"(da + soff[i]), "l"(gA[i] + st * 32));
            asm volatile("cp.async.ca.shared.global [%0], [%1], 16;"
                         :: "r"(db + soff[i]), "l"(gB[i] + st * 32));
        }
        asm volatile("cp.async.commit_group;");
    }

    for (int c = 0; c < KCH; c++) {
        const int buf = c % 3;
        if (c + 1 < KCH) asm volatile("cp.async.wait_group 1;");
        else             asm volatile("cp.async.wait_group 0;");
        __syncthreads();
        if (c + 2 < KCH) {
            const int wb = (c + 2) % 3;
            const uint32_t da = sAu + wb * 8192, db = sBu + wb * 8192;
            #pragma unroll
            for (int i = 0; i < 2; i++) {
                asm volatile("cp.async.ca.shared.global [%0], [%1], 16;"
                             :: "r"(da + soff[i]), "l"(gA[i] + (c + 2) * 32));
                asm volatile("cp.async.ca.shared.global [%0], [%1], 16;"
                             :: "r"(db + soff[i]), "l"(gB[i] + (c + 2) * 32));
            }
            asm volatile("cp.async.commit_group;");
        }

        const uint32_t baseA = sAu + buf * 8192;
        const uint32_t baseB = sBu + buf * 8192;
        #pragma unroll
        for (int s = 0; s < 2; s++) {
            uint32_t afr[2][4];
            #pragma unroll
            for (int mt = 0; mt < 2; mt++) {
                asm volatile("ldmatrix.sync.aligned.m8n8.x4.shared.b16 "
                             "{%0,%1,%2,%3}, [%4];"
                             : "=r"(afr[mt][0]), "=r"(afr[mt][1]),
                               "=r"(afr[mt][2]), "=r"(afr[mt][3])
                             : "r"(baseA + aoff[s][mt]));
            }
            uint32_t bfr[8][2];
            #pragma unroll
            for (int nb = 0; nb < 4; nb++) {
                uint32_t r0, r1, r2, r3;
                asm volatile("ldmatrix.sync.aligned.m8n8.x4.shared.b16 "
                             "{%0,%1,%2,%3}, [%4];"
                             : "=r"(r0), "=r"(r1), "=r"(r2), "=r"(r3)
                             : "r"(baseB + boff[s][nb]));
                bfr[nb * 2][0] = r0;     bfr[nb * 2][1] = r2;
                bfr[nb * 2 + 1][0] = r1; bfr[nb * 2 + 1][1] = r3;
            }
            #pragma unroll
            for (int mt = 0; mt < 2; mt++)
                #pragma unroll
                for (int nt = 0; nt < 8; nt++) {
                    asm volatile(
                        "mma.sync.aligned.m16n8k16.row.col.f32.f16.f16.f32 "
                        "{%0,%1,%2,%3}, {%4,%5,%6,%7}, {%8,%9}, {%0,%1,%2,%3};"
                        : "+f"(acc[mt][nt][0]), "+f"(acc[mt][nt][1]),
                          "+f"(acc[mt][nt][2]), "+f"(acc[mt][nt][3])
                        : "r"(afr[mt][0]), "r"(afr[mt][1]),
                          "r"(afr[mt][2]), "r"(afr[mt][3]),
                          "r"(bfr[nt][0]), "r"(bfr[nt][1]));
                }
        }
    }

    float gate = 0.f, omg = 1.f;
    if (emode == 1) {
        gate = 1.0f / (1.0f + expf(-gatep[0]));
        omg = 1.0f - gate;
    }
    #pragma unroll
    for (int mt = 0; mt < 2; mt++) {
        #pragma unroll
        for (int half = 0; half < 2; half++) {
            int row = m0 + wm * 32 + mt * 16 + (lane >> 2) + 8 * half;
            float rsv = 0.f; const float* nqr = nullptr;
            __half* arow2 = nullptr;
            if (emode == 1) {
                rsv = g_rowsum[row];
                nqr = nq + (size_t)(row & 15) * DN;
                arow2 = (__half*)g_Abf2 + (size_t)row * KH;
            }
            float* crow = C + (size_t)row * Ncols;
            #pragma unroll
            for (int nt = 0; nt < 8; nt++) {
                int col = n0 + wn * 64 + nt * 8 + (lane & 3) * 2;
                float v0 = acc[mt][nt][half * 2 + 0];
                float v1 = acc[mt][nt][half * 2 + 1];
                if (emode == 1) {
                    v0 += rsv * __ldg(&bias[col]);
                    v1 += rsv * __ldg(&bias[col + 1]);
                    v0 = omg * v0 + gate * __ldg(&nqr[col]);
                    v1 = omg * v1 + gate * __ldg(&nqr[col + 1]);
                    *(unsigned*)(arow2 + col) = packh2(v0, v1);
                } else if (emode == 2) {
                    v0 += __ldg(&bias[col]);
                    v1 += __ldg(&bias[col + 1]);
                }
                float2 o; o.x = v0; o.y = v1;
                *(float2*)(crow + col) = o;
            }
        }
    }
}

// ---------------- kEdgeP: partial edge logits, float4 inner ---------------
__global__ void kEdgeP(const float* __restrict__ be1, const float* __restrict__ We2) {
    int b = blockIdx.x;
    int h0 = blockIdx.y * 256;
    int tid = threadIdx.x;
    int i = tid >> 4, j = tid & 15;
    __shared__ __align__(16) float sHi[KK * 260];
    __shared__ __align__(16) float sHj[KK * 260];
    __shared__ __align__(16) float sW2[256];

    for (int idx = tid; idx < KK * 256; idx += 256) {
        int r = idx >> 8, c = idx & 255;
        sHi[r * 260 + c] = g_H[(size_t)(b * KK + r) * (2 * HID) + h0 + c] + be1[h0 + c];
        sHj[r * 260 + c] = g_H[(size_t)(b * KK + r) * (2 * HID) + HID + h0 + c];
    }
    sW2[tid] = We2[h0 + tid];
    __syncthreads();
    const float* hi = sHi + i * 260;
    const float* hj = sHj + j * 260;
    float a0 = 0.f, a1 = 0.f, a2 = 0.f, a3 = 0.f;
    #pragma unroll 4
    for (int c = 0; c < 256; c += 4) {
        float4 h4 = *(const float4*)&hi[c];
        float4 g4 = *(const float4*)&hj[c];
        float4 w4 = *(const float4*)&sW2[c];
        a0 += fmaxf(h4.x + g4.x, 0.f) * w4.x;
        a1 += fmaxf(h4.y + g4.y, 0.f) * w4.y;
        a2 += fmaxf(h4.z + g4.z, 0.f) * w4.z;
        a3 += fmaxf(h4.w + g4.w, 0.f) * w4.w;
    }
    g_Ep[blockIdx.y][b * 256 + tid] = (a0 + a1) + (a2 + a3);
}

// ---------------- kEdgeR: combine partials -> outE ------------------------
__global__ void kEdgeR(const float* __restrict__ be2, float* __restrict__ outE) {
    int b = blockIdx.x;
    int tid = threadIdx.x;
    outE[b * 256 + tid] = g_Ep[0][b * 256 + tid] + g_Ep[1][b * 256 + tid] + be2[0];
}

// ---------------- kMsg: A-softmax from g_Ep, V += relu(A@M), fp16 V -------
__global__ void kMsg(const float* __restrict__ be2, float* __restrict__ outV) {
    int b = blockIdx.x, dh = blockIdx.y;
    int tid = threadIdx.x;
    int d = dh * 256 + tid;
    __shared__ float sE[KK * 17];
    __shared__ float sAm[KK * 17];
    int i = tid >> 4, j = tid & 15;
    float E = g_Ep[0][b * 256 + tid] + g_Ep[1][b * 256 + tid] + be2[0];
    sE[i * 17 + j] = E;
    __syncthreads();
    {
        float m = -3.4e38f;
        #pragma unroll
        for (int jj = 0; jj < KK; jj++) m = fmaxf(m, sE[i * 17 + jj]);
        float s = 0.f;
        #pragma unroll
        for (int jj = 0; jj < KK; jj++) s += __expf(sE[i * 17 + jj] - m);
        sAm[i * 17 + j] = __expf(E - m) / s;
    }
    __syncthreads();
    float mv[KK];
    #pragma unroll
    for (int jj = 0; jj < KK; jj++)
        mv[jj] = g_M[(size_t)(b * KK + jj) * DN + d];
    #pragma unroll
    for (int ii = 0; ii < KK; ii++) {
        const float* arow = sAm + ii * 17;
        float acc = 0.f;
        #pragma unroll
        for (int jj = 0; jj < KK; jj++) acc += arow[jj] * mv[jj];
        int row = b * KK + ii;
        float nv = g_V[(size_t)row * DN + d] + fmaxf(acc, 0.f);
        g_V[(size_t)row * DN + d] = nv;
        ((__half*)g_Abf2)[(size_t)row * KH + d] = __float2half_rn(nv);
        if (outV) outV[(size_t)row * DN + d] = nv;
    }
}

// ---------------- host ----------------------------------------------------
extern "C" void kernel_launch(void* const* d_in, const int* in_sizes, int n_in,
                              void* d_out, int out_size) {
    const float* w    = (const float*)d_in[0];
    const int*   mask = (const int*)  d_in[1];
    const float* nq   = (const float*)d_in[2];
    const float* Wq   = (const float*)d_in[3];
    const float* bq   = (const float*)d_in[4];
    const float* Wk   = (const float*)d_in[5];
    const float* bk   = (const float*)d_in[6];
    const float* Wv   = (const float*)d_in[7];
    const float* bv   = (const float*)d_in[8];
    const float* We1  = (const float*)d_in[9];
    const float* be1  = (const float*)d_in[10];
    const float* We2  = (const float*)d_in[11];
    const float* be2  = (const float*)d_in[12];
    const float* fg   = (const float*)d_in[13];
    const float* Wg   = (const float*)d_in[14];
    const float* bg   = (const float*)d_in[15];

    float* outS = (float*)d_out;
    float* outV = outS + (size_t)BB * NN * KK;
    float* outE = outV + (size_t)BB * KK * DN;

    kPrep<<<PREP_SPLIT + PREP_KQ, 256>>>(Wv, Wg, We1, nq, Wq);
    kQr<<<48, 256>>>(bq);
    kP<<<96, 256>>>(Wk, bk);                                   // g_Pth fp16 + c
    kScoreG<<<308, 256>>>(w);                                  // fused w->fp16 + scores
    kU<<<dim3(BB, 4), 96>>>(mask, outS);                       // softmax + fp16 U

    kTGemm<<<dim3(32, 6), 256>>>(0, 0, 1, bv, nq, fg);         // V = U@Wv; fp16 V -> Abf2
    kTGemm<<<dim3(32, 14), 256>>>(1, 0, 3, bg, nullptr, nullptr);   // H = V@We1 AND M = V@Wg0+bg0
    kEdgeP<<<dim3(BB, 2), 256>>>(be1, We2);                    // partial E
    kMsg<<<dim3(BB, 3), 256>>>(be2, nullptr);                  // A inline; V += relu(A@M)
    kTGemm<<<dim3(32, 6), 256>>>(1, 2, 2, bg + DN, nullptr, nullptr); // M = V@Wg1+bg1
    kMsg<<<dim3(BB, 3), 256>>>(be2, outV);                     // final V; Abf2; outV
    kTGemm<<<dim3(32, 8), 256>>>(1, 3, 0, nullptr, nullptr, nullptr); // H on final V
    kEdgeP<<<dim3(BB, 2), 256>>>(be1, We2);                    // partial E (final V)
    kEdgeR<<<BB, 256>>>(be2, outE);                            // E -> out
}

// round 16
// speedup vs baseline: 1.0181x; 1.0181x over previous
#include <cuda_runtime.h>
#include <cuda_bf16.h>
#include <cuda_fp16.h>
#include <math.h>
#include <stdint.h>

// Problem dims
#define BB 256
#define NN 77
#define DD 768
#define KK 16
#define DN 768
#define HID 512
#define MTOT (BB*KK)          // 4096
#define SCALE 0.10206207261596575f   // (768/8)^-0.5
#define KH 768                // GEMM K (fp16)
#define KCH 24                // 768/32 chunks
#define MSC (BB*NN)           // 19712 score rows = 308*64

// ---------------- scratch (device globals; no allocation) ----------------
__device__ float g_Qp[16][KK*DN];
__device__ float g_Q[KK*DN];
__device__ float g_c[KK];
__device__ float g_Sc[(size_t)MSC*KK];   // raw scores [m][k]
__device__ float g_Ep[2][BB*256];        // partial edge logits
__device__ float g_V[MTOT*DN];
__device__ float g_rowsum[MTOT];
__device__ float g_H[MTOT*2*HID];
__device__ float g_M[MTOT*DN];
// fp16 operand buffers (uint4 for 16B alignment)
__device__ uint4 g_wh [(size_t)MSC*DD/8];     // fp16 copy of w
__device__ uint4 g_Pth[KK*DN/8];              // fp16 P, node-major [16][768]
__device__ uint4 g_Abf [(size_t)MTOT*KH/8];   // fp16 U
__device__ uint4 g_Abf2[(size_t)MTOT*KH/8];   // fp16 V
__device__ uint4 g_WbfV [768*KH/8];
__device__ uint4 g_WbfG0[768*KH/8];
__device__ uint4 g_WbfG1[768*KH/8];
__device__ uint4 g_WbfE1[1024*KH/8];

__device__ __forceinline__ uint32_t smem_u32(const void* p) {
    uint32_t a;
    asm("{ .reg .u64 t; cvta.to.shared.u64 t, %1; cvt.u32.u64 %0, t; }"
        : "=r"(a) : "l"(p));
    return a;
}

__device__ __forceinline__ unsigned packh2(float a, float b) {
    __half2 h = __floats2half2_rn(a, b);
    return *(unsigned*)&h;
}

// ---------------- kPrep: fused w->fp16, weight conversions, kQ partials ---
#define PREP_WH 7392
#define PREP_SPLIT 1248
#define PREP_KQ 48
__global__ void kPrep(const float* __restrict__ w,
                      const float* __restrict__ Wv,
                      const float* __restrict__ Wg,
                      const float* __restrict__ We1,
                      const float* __restrict__ nq,
                      const float* __restrict__ Wq) {
    int bid = blockIdx.x;
    int tid = threadIdx.x;
    if (bid < PREP_WH) {
        size_t idx = (size_t)bid * 256 + tid;
        const float4* s = (const float4*)w + idx * 2;
        float4 a = s[0], b = s[1];
        uint4 o;
        o.x = packh2(a.x, a.y); o.y = packh2(a.z, a.w);
        o.z = packh2(b.x, b.y); o.w = packh2(b.z, b.w);
        g_wh[idx] = o;
    } else if (bid < PREP_WH + PREP_SPLIT) {
        int sid = (bid - PREP_WH) * 256 + tid;
        float a[8];
        __half* out;
        int e0;
        if (sid < 221184) {
            int job = sid / 73728, s = sid % 73728;
            int n = s % 768, seg = s / 768;
            e0 = seg * 8;
            const float* Wp = (job == 0) ? Wv : (job == 1) ? Wg : (Wg + 768 * 768);
            uint4* o4 = (job == 0) ? g_WbfV : (job == 1) ? g_WbfG0 : g_WbfG1;
            out = (__half*)o4 + (size_t)n * KH;
            #pragma unroll
            for (int i = 0; i < 8; i++) a[i] = Wp[(size_t)(e0 + i) * 768 + n];
        } else {
            int s = sid - 221184;
            int n = s % 1024, seg = s / 1024;
            e0 = seg * 8;
            out = (__half*)g_WbfE1 + (size_t)n * KH;
            size_t base = (n < HID) ? (size_t)n : ((size_t)768 * HID + (n - HID));
            #pragma unroll
            for (int i = 0; i < 8; i++) a[i] = We1[base + (size_t)(e0 + i) * HID];
        }
        unsigned h[4];
        #pragma unroll
        for (int i = 0; i < 4; i++) h[i] = packh2(a[2 * i], a[2 * i + 1]);
        *(uint4*)(out + e0) = *(uint4*)h;
    } else {
        int q = bid - (PREP_WH + PREP_SPLIT);
        int dblk = q % 3, sl = q / 3;
        int d = dblk * 256 + tid;
        int e0 = sl * 48;
        __shared__ float snq[KK][48];
        for (int idx = tid; idx < KK * 48; idx += 256)
            snq[idx / 48][idx % 48] = nq[(idx / 48) * DN + e0 + idx % 48];
        __syncthreads();
        float acc[KK];
        #pragma unroll
        for (int k = 0; k < KK; k++) acc[k] = 0.f;
        const float* wp = Wq + (size_t)e0 * DN + d;
        #pragma unroll 4
        for (int e = 0; e < 48; e++) {
            float wv = wp[(size_t)e * DN];
            #pragma unroll
            for (int k = 0; k < KK; k++) acc[k] += snq[k][e] * wv;
        }
        #pragma unroll
        for (int k = 0; k < KK; k++) g_Qp[sl][k * DN + d] = acc[k];
    }
}

// ---------------- kQr: sum 16 partials + bq -> g_Q ------------------------
__global__ void kQr(const float* __restrict__ bq) {
    int i = blockIdx.x * 256 + threadIdx.x;   // 12288
    float s = bq[i % DN];
    #pragma unroll
    for (int sl = 0; sl < 16; sl++) s += g_Qp[sl][i];
    g_Q[i] = s;
}

// ---------------- kP: P -> fp16 g_Pth directly; c[k] ----------------------
__global__ void kP(const float* __restrict__ Wk, const float* __restrict__ bk) {
    __shared__ float sQ[KK][DN];   // 48 KB
    __shared__ float sPo[8][17];
    int tid = threadIdx.x;
    int lane = tid & 31, warp = tid >> 5;
    for (int idx = tid; idx < KK * DN; idx += 256)
        sQ[idx / DN][idx % DN] = g_Q[idx];
    __syncthreads();

    int j = blockIdx.x * 8 + warp;
    const float4* wr = (const float4*)(Wk + (size_t)j * DN);
    float acc[KK];
    #pragma unroll
    for (int k = 0; k < KK; k++) acc[k] = 0.f;
    #pragma unroll
    for (int it = 0; it < 6; it++) {
        int e = it * 128 + lane * 4;
        float4 wv = wr[it * 32 + lane];
        #pragma unroll
        for (int k = 0; k < KK; k++) {
            float4 qv = *(const float4*)&sQ[k][e];
            acc[k] += wv.x * qv.x + wv.y * qv.y + wv.z * qv.z + wv.w * qv.w;
        }
    }
    float out = 0.f;
    #pragma unroll
    for (int k = 0; k < KK; k++) {
        float v = acc[k];
        v += __shfl_xor_sync(0xFFFFFFFFu, v, 16);
        v += __shfl_xor_sync(0xFFFFFFFFu, v, 8);
        v += __shfl_xor_sync(0xFFFFFFFFu, v, 4);
        v += __shfl_xor_sync(0xFFFFFFFFu, v, 2);
        v += __shfl_xor_sync(0xFFFFFFFFu, v, 1);
        if (lane == k) out = v;
    }
    if (lane < KK) sPo[warp][lane] = out;   // sPo[jj][k]
    __syncthreads();
    if (tid < 128) {
        int k = tid >> 3, jj = tid & 7;
        ((__half*)g_Pth)[k * DN + blockIdx.x * 8 + jj] = __float2half_rn(sPo[jj][k]);
    }

    if (blockIdx.x >= 94) {
        int k = (blockIdx.x - 94) * 8 + warp;
        float cc = 0.f;
        #pragma unroll
        for (int it = 0; it < 6; it++) {
            int e = it * 128 + lane * 4;
            float4 bv = *(const float4*)(bk + e);
            float4 qv = *(const float4*)&sQ[k][e];
            cc += bv.x * qv.x + bv.y * qv.y + bv.z * qv.z + bv.w * qv.w;
        }
        cc += __shfl_xor_sync(0xFFFFFFFFu, cc, 16);
        cc += __shfl_xor_sync(0xFFFFFFFFu, cc, 8);
        cc += __shfl_xor_sync(0xFFFFFFFFu, cc, 4);
        cc += __shfl_xor_sync(0xFFFFFFFFu, cc, 2);
        cc += __shfl_xor_sync(0xFFFFFFFFu, cc, 1);
        if (lane == 0) g_c[k] = cc;
    }
}

// ---------------- kScoreG: scores = wh @ Pth^T, 64-row tiles --------------
// grid 308, block 128 (4 warps, all compute); cp.async 3-stage A pipeline
__global__ __launch_bounds__(128) void kScoreG() {
    __shared__ __align__(1024) __half sB[16 * 768];   // 24 KB, resident
    __shared__ __align__(1024) __half sA[3][64 * 32]; // 12 KB, 3-stage

    const __half* Ag = (const __half*)g_wh;
    const int m0 = blockIdx.x * 64;
    const int tid = threadIdx.x;
    const int lane = tid & 31, warp = tid >> 5;   // warp 0..3
    const uint32_t sAu = smem_u32(sA), sBu = smem_u32(sB);

    // load B (16 nodes x 768 fp16) with unit-XOR swizzle
    for (int idx = tid; idx < 16 * 96; idx += 128) {
        int r = idx / 96, u = idx % 96;
        uint4 v = g_Pth[r * 96 + u];
        *(uint4*)((char*)sB + r * 1536 + ((u ^ (r & 7)) << 4)) = v;
    }

    // A staging slots: 2 x 16B per thread per chunk (64 rows x 4 quads)
    uint32_t soff[2];
    const __half* gA[2];
    #pragma unroll
    for (int i = 0; i < 2; i++) {
        int v = tid * 2 + i, row = v >> 2, q = v & 3;
        soff[i] = row * 64 + ((q ^ ((row >> 1) & 3)) << 4);
        gA[i] = Ag + (size_t)(m0 + row) * KH + q * 8;
    }

    const int r16 = lane & 15, hh = lane >> 4;
    uint32_t aoff[2];
    #pragma unroll
    for (int s = 0; s < 2; s++) {
        int quad = 2 * s + hh;
        int row = warp * 16 + r16;
        aoff[s] = row * 64 + ((quad ^ ((row >> 1) & 3)) << 4);
    }

    float acc[2][4];
    #pragma unroll
    for (int b = 0; b < 2; b++)
        #pragma unroll
        for (int r = 0; r < 4; r++) acc[b][r] = 0.f;

    #pragma unroll
    for (int st = 0; st < 2; st++) {
        uint32_t da = sAu + st * 4096;
        #pragma unroll
        for (int i = 0; i < 2; i++)
            asm volatile("cp.async.ca.shared.global [%0], [%1], 16;"
                         :: "r"(da + soff[i]), "l"(gA[i] + st * 32));
        asm volatile("cp.async.commit_group;");
    }
    __syncthreads();   // B visible

    for (int c = 0; c < KCH; c++) {
        const int buf = c % 3;
        if (c + 1 < KCH) asm volatile("cp.async.wait_group 1;");
        else             asm volatile("cp.async.wait_group 0;");
        __syncthreads();
        if (c + 2 < KCH) {
            const uint32_t da = sAu + ((c + 2) % 3) * 4096;
            #pragma unroll
            for (int i = 0; i < 2; i++)
                asm volatile("cp.async.ca.shared.global [%0], [%1], 16;"
                             :: "r"(da + soff[i]), "l"(gA[i] + (c + 2) * 32));
            asm volatile("cp.async.commit_group;");
        }

        const uint32_t baseA = sAu + buf * 4096;
        #pragma unroll
        for (int s = 0; s < 2; s++) {
            uint32_t afr[4];
            asm volatile("ldmatrix.sync.aligned.m8n8.x4.shared.b16 "
                         "{%0,%1,%2,%3}, [%4];"
                         : "=r"(afr[0]), "=r"(afr[1]), "=r"(afr[2]), "=r"(afr[3])
                         : "r"(baseA + aoff[s]));
            int u = c * 4 + s * 2 + hh;
            uint32_t baddr = sBu + r16 * 1536 + ((u ^ (r16 & 7)) << 4);
            uint32_t r0, r1, r2, r3;
            asm volatile("ldmatrix.sync.aligned.m8n8.x4.shared.b16 "
                         "{%0,%1,%2,%3}, [%4];"
                         : "=r"(r0), "=r"(r1), "=r"(r2), "=r"(r3) : "r"(baddr));
            uint32_t bfr[2][2];
            bfr[0][0] = r0; bfr[0][1] = r2;
            bfr[1][0] = r1; bfr[1][1] = r3;
            #pragma unroll
            for (int nt = 0; nt < 2; nt++) {
                asm volatile(
                    "mma.sync.aligned.m16n8k16.row.col.f32.f16.f16.f32 "
                    "{%0,%1,%2,%3}, {%4,%5,%6,%7}, {%8,%9}, {%0,%1,%2,%3};"
                    : "+f"(acc[nt][0]), "+f"(acc[nt][1]),
                      "+f"(acc[nt][2]), "+f"(acc[nt][3])
                    : "r"(afr[0]), "r"(afr[1]), "r"(afr[2]), "r"(afr[3]),
                      "r"(bfr[nt][0]), "r"(bfr[nt][1]));
            }
        }
    }

    #pragma unroll
    for (int half = 0; half < 2; half++) {
        int row = m0 + warp * 16 + (lane >> 2) + 8 * half;
        float* crow = g_Sc + (size_t)row * KK;
        #pragma unroll
        for (int nt = 0; nt < 2; nt++) {
            int col = nt * 8 + (lane & 3) * 2;
            crow[col]     = acc[nt][half * 2 + 0];
            crow[col + 1] = acc[nt][half * 2 + 1];
        }
    }
}

// ---------------- kU: softmax (from g_Sc) + U = S^T w, fp16 U out ---------
__global__ void kU(const int* __restrict__ mask, float* __restrict__ outS) {
    int b = blockIdx.x, dh = blockIdx.y;
    int tid = threadIdx.x;
    int d0 = dh * 192 + tid * 2;
    __shared__ float sS[NN * KK];
    __shared__ float sC[KK];
    if (tid < KK) sC[tid] = g_c[tid];
    __syncthreads();
    if (tid < NN) {
        int n = tid;
        float v[KK];
        const float4* src = (const float4*)(g_Sc + (size_t)(b * NN + n) * KK);
        #pragma unroll
        for (int q = 0; q < 4; q++) *(float4*)&v[q * 4] = src[q];
        if (mask[b * NN + n] == 0) {
            #pragma unroll
            for (int k = 0; k < KK; k++) sS[n * KK + k] = 1.0f / 16.0f;
        } else {
            float sc[KK]; float m = -3.4e38f;
            #pragma unroll
            for (int k = 0; k < KK; k++) { sc[k] = (v[k] + sC[k]) * SCALE; m = fmaxf(m, sc[k]); }
            float e[KK]; float s = 0.f;
            #pragma unroll
            for (int k = 0; k < KK; k++) { e[k] = __expf(sc[k] - m); s += e[k]; }
            float inv = 1.0f / s;
            #pragma unroll
            for (int k = 0; k < KK; k++) sS[n * KK + k] = e[k] * inv;
        }
        if (dh == 0) {
            float4* dst = (float4*)(outS + (size_t)(b * NN + n) * KK);
            #pragma unroll
            for (int q = 0; q < 4; q++) dst[q] = *(float4*)&sS[n * KK + q * 4];
        }
    }
    __syncthreads();
    if (dh == 0 && tid < KK) {
        float s = 0.f;
        for (int n = 0; n < NN; n++) s += sS[n * KK + tid];
        g_rowsum[b * KK + tid] = s;
    }

    float2 acc[KK];
    #pragma unroll
    for (int k = 0; k < KK; k++) { acc[k].x = 0.f; acc[k].y = 0.f; }
    const __half* wp = (const __half*)g_wh + (size_t)b * NN * DD + d0;
    #pragma unroll 4
    for (int n = 0; n < NN; n++) {
        __half2 hv = *(const __half2*)(wp + (size_t)n * DD);
        float2 wv = __half22float2(hv);
        const float* srow = sS + n * KK;
        #pragma unroll
        for (int k = 0; k < KK; k++) {
            float s = srow[k];
            acc[k].x += s * wv.x; acc[k].y += s * wv.y;
        }
    }
    #pragma unroll
    for (int k = 0; k < KK; k++) {
        __half* ur = (__half*)g_Abf + (size_t)(b * KK + k) * KH;
        *(unsigned*)(ur + d0) = packh2(acc[k].x, acc[k].y);
    }
}

// ---------------- kTGemm: mma.sync fp16 GEMM ------------------------------
__global__ __launch_bounds__(256, 2) void kTGemm(
    int asel, int wsel, int mode, const float* __restrict__ bias,
    const float* __restrict__ nq, const float* __restrict__ gatep)
{
    __shared__ __align__(1024) __half sA[3][128 * 32];
    __shared__ __align__(1024) __half sB[3][128 * 32];

    const __half* Ag = (const __half*)(asel ? g_Abf2 : g_Abf);
    const int m0 = blockIdx.x * 128;
    int n0 = blockIdx.y * 128;
    const __half* Bg;
    float* C; int Ncols; int emode = mode;
    if (mode == 3) {
        if (blockIdx.y < 8) {
            Bg = (const __half*)g_WbfE1; C = g_H; Ncols = 2 * HID; emode = 0;
        } else {
            n0 = (blockIdx.y - 8) * 128;
            Bg = (const __half*)g_WbfG0; C = g_M; Ncols = DN; emode = 2;
        }
    } else {
        const uint4* B4 = (wsel == 0) ? g_WbfV : (wsel == 1) ? g_WbfG0
                        : (wsel == 2) ? g_WbfG1 : g_WbfE1;
        Bg = (const __half*)B4;
        if (mode == 0)      { C = g_H; Ncols = 2 * HID; }
        else if (mode == 1) { C = g_V; Ncols = DN; }
        else                { C = g_M; Ncols = DN; }
    }

    const int tid = threadIdx.x;
    const int lane = tid & 31, warp = tid >> 5;
    const int wm = warp >> 1, wn = warp & 1;

    const uint32_t sAu = smem_u32(sA), sBu = smem_u32(sB);

    uint32_t soff[2];
    const __half* gA[2];
    const __half* gB[2];
    #pragma unroll
    for (int i = 0; i < 2; i++) {
        int v = tid * 2 + i, row = v >> 2, q = v & 3;
        soff[i] = row * 64 + ((q ^ ((row >> 1) & 3)) << 4);
        gA[i] = Ag + (size_t)(m0 + row) * KH + q * 8;
        gB[i] = Bg + (size_t)(n0 + row) * KH + q * 8;
    }

    const int r16 = lane & 15, hh = lane >> 4;
    uint32_t aoff[2][2], boff[2][4];
    #pragma unroll
    for (int s = 0; s < 2; s++) {
        int quad = 2 * s + hh;
        #pragma unroll
        for (int mt = 0; mt < 2; mt++) {
            int row = wm * 32 + mt * 16 + r16;
            aoff[s][mt] = row * 64 + ((quad ^ ((row >> 1) & 3)) << 4);
        }
        #pragma unroll
        for (int nb = 0; nb < 4; nb++) {
            int row = wn * 64 + nb * 16 + r16;
            boff[s][nb] = row * 64 + ((quad ^ ((row >> 1) & 3)) << 4);
        }
    }

    float acc[2][8][4];
    #pragma unroll
    for (int a = 0; a < 2; a++)
        #pragma unroll
        for (int b = 0; b < 8; b++)
            #pragma unroll
            for (int r = 0; r < 4; r++) acc[a][b][r] = 0.f;

    #pragma unroll
    for (int st = 0; st < 2; st++) {
        uint32_t da = sAu + st * 8192, db = sBu + st * 8192;
        #pragma unroll
        for (int i = 0; i < 2; i++) {
            asm volatile("cp.async.ca.shared.global [%0], [%1], 16;"
                         :: "r"(da + soff[i]), "l"(gA[i] + st * 32));
            asm volatile("cp.async.ca.shared.global [%0], [%1], 16;"
                         :: "r"(db + soff[i]), "l"(gB[i] + st * 32));
        }
        asm volatile("cp.async.commit_group;");
    }

    for (int c = 0; c < KCH; c++) {
        const int buf = c % 3;
        if (c + 1 < KCH) asm volatile("cp.async.wait_group 1;");
        else             asm volatile("cp.async.wait_group 0;");
        __syncthreads();
        if (c + 2 < KCH) {
            const int wb = (c + 2) % 3;
            const uint32_t da = sAu + wb * 8192, db = sBu + wb * 8192;
            #pragma unroll
            for (int i = 0; i < 2; i++) {
                asm volatile("cp.async.ca.shared.global [%0], [%1], 16;"
                             :: "r"(da + soff[i]), "l"(gA[i] + (c + 2) * 32));
                asm volatile("cp.async.ca.shared.global [%0], [%1], 16;"
                             :: "r"(db + soff[i]), "l"(gB[i] + (c + 2) * 32));
            }
            asm volatile("cp.async.commit_group;");
        }

        const uint32_t baseA = sAu + buf * 8192;
        const uint32_t baseB = sBu + buf * 8192;
        #pragma unroll
        for (int s = 0; s < 2; s++) {
            uint32_t afr[2][4];
            #pragma unroll
            for (int mt = 0; mt < 2; mt++) {
                asm volatile("ldmatrix.sync.aligned.m8n8.x4.shared.b16 "
                             "{%0,%1,%2,%3}, [%4];"
                             : "=r"(afr[mt][0]), "=r"(afr[mt][1]),
                               "=r"(afr[mt][2]), "=r"(afr[mt][3])
                             : "r"(baseA + aoff[s][mt]));
            }
            uint32_t bfr[8][2];
            #pragma unroll
            for (int nb = 0; nb < 4; nb++) {
                uint32_t r0, r1, r2, r3;
                asm volatile("ldmatrix.sync.aligned.m8n8.x4.shared.b16 "
                             "{%0,%1,%2,%3}, [%4];"
                             : "=r"(r0), "=r"(r1), "=r"(r2), "=r"(r3)
                             : "r"(baseB + boff[s][nb]));
                bfr[nb * 2][0] = r0;     bfr[nb * 2][1] = r2;
                bfr[nb * 2 + 1][0] = r1; bfr[nb * 2 + 1][1] = r3;
            }
            #pragma unroll
            for (int mt = 0; mt < 2; mt++)
                #pragma unroll
                for (int nt = 0; nt < 8; nt++) {
                    asm volatile(
                        "mma.sync.aligned.m16n8k16.row.col.f32.f16.f16.f32 "
                        "{%0,%1,%2,%3}, {%4,%5,%6,%7}, {%8,%9}, {%0,%1,%2,%3};"
                        : "+f"(acc[mt][nt][0]), "+f"(acc[mt][nt][1]),
                          "+f"(acc[mt][nt][2]), "+f"(acc[mt][nt][3])
                        : "r"(afr[mt][0]), "r"(afr[mt][1]),
                          "r"(afr[mt][2]), "r"(afr[mt][3]),
                          "r"(bfr[nt][0]), "r"(bfr[nt][1]));
                }
        }
    }

    float gate = 0.f, omg = 1.f;
    if (emode == 1) {
        gate = 1.0f / (1.0f + expf(-gatep[0]));
        omg = 1.0f - gate;
    }
    #pragma unroll
    for (int mt = 0; mt < 2; mt++) {
        #pragma unroll
        for (int half = 0; half < 2; half++) {
            int row = m0 + wm * 32 + mt * 16 + (lane >> 2) + 8 * half;
            float rsv = 0.f; const float* nqr = nullptr;
            __half* arow2 = nullptr;
            if (emode == 1) {
                rsv = g_rowsum[row];
                nqr = nq + (size_t)(row & 15) * DN;
                arow2 = (__half*)g_Abf2 + (size_t)row * KH;
            }
            float* crow = C + (size_t)row * Ncols;
            #pragma unroll
            for (int nt = 0; nt < 8; nt++) {
                int col = n0 + wn * 64 + nt * 8 + (lane & 3) * 2;
                float v0 = acc[mt][nt][half * 2 + 0];
                float v1 = acc[mt][nt][half * 2 + 1];
                if (emode == 1) {
                    v0 += rsv * __ldg(&bias[col]);
                    v1 += rsv * __ldg(&bias[col + 1]);
                    v0 = omg * v0 + gate * __ldg(&nqr[col]);
                    v1 = omg * v1 + gate * __ldg(&nqr[col + 1]);
                    *(unsigned*)(arow2 + col) = packh2(v0, v1);
                } else if (emode == 2) {
                    v0 += __ldg(&bias[col]);
                    v1 += __ldg(&bias[col + 1]);
                }
                float2 o; o.x = v0; o.y = v1;
                *(float2*)(crow + col) = o;
            }
        }
    }
}

// ---------------- kEdgeP: partial edge logits, float4 inner ---------------
__global__ void kEdgeP(const float* __restrict__ be1, const float* __restrict__ We2) {
    int b = blockIdx.x;
    int h0 = blockIdx.y * 256;
    int tid = threadIdx.x;
    int i = tid >> 4, j = tid & 15;
    __shared__ __align__(16) float sHi[KK * 260];
    __shared__ __align__(16) float sHj[KK * 260];
    __shared__ __align__(16) float sW2[256];

    for (int idx = tid; idx < KK * 256; idx += 256) {
        int r = idx >> 8, c = idx & 255;
        sHi[r * 260 + c] = g_H[(size_t)(b * KK + r) * (2 * HID) + h0 + c] + be1[h0 + c];
        sHj[r * 260 + c] = g_H[(size_t)(b * KK + r) * (2 * HID) + HID + h0 + c];
    }
    sW2[tid] = We2[h0 + tid];
    __syncthreads();
    const float* hi = sHi + i * 260;
    const float* hj = sHj + j * 260;
    float a0 = 0.f, a1 = 0.f, a2 = 0.f, a3 = 0.f;
    #pragma unroll 4
    for (int c = 0; c < 256; c += 4) {
        float4 h4 = *(const float4*)&hi[c];
        float4 g4 = *(const float4*)&hj[c];
        float4 w4 = *(const float4*)&sW2[c];
        a0 += fmaxf(h4.x + g4.x, 0.f) * w4.x;
        a1 += fmaxf(h4.y + g4.y, 0.f) * w4.y;
        a2 += fmaxf(h4.z + g4.z, 0.f) * w4.z;
        a3 += fmaxf(h4.w + g4.w, 0.f) * w4.w;
    }
    g_Ep[blockIdx.y][b * 256 + tid] = (a0 + a1) + (a2 + a3);
}

// ---------------- kEdgeR: combine partials -> outE ------------------------
__global__ void kEdgeR(const float* __restrict__ be2, float* __restrict__ outE) {
    int b = blockIdx.x;
    int tid = threadIdx.x;
    outE[b * 256 + tid] = g_Ep[0][b * 256 + tid] + g_Ep[1][b * 256 + tid] + be2[0];
}

// ---------------- kMsg: A-softmax from g_Ep, V += relu(A@M), fp16 V -------
__global__ void kMsg(const float* __restrict__ be2, float* __restrict__ outV) {
    int b = blockIdx.x, dh = blockIdx.y;
    int tid = threadIdx.x;
    int d = dh * 256 + tid;
    __shared__ float sE[KK * 17];
    __shared__ float sAm[KK * 17];
    int i = tid >> 4, j = tid & 15;
    float E = g_Ep[0][b * 256 + tid] + g_Ep[1][b * 256 + tid] + be2[0];
    sE[i * 17 + j] = E;
    __syncthreads();
    {
        float m = -3.4e38f;
        #pragma unroll
        for (int jj = 0; jj < KK; jj++) m = fmaxf(m, sE[i * 17 + jj]);
        float s = 0.f;
        #pragma unroll
        for (int jj = 0; jj < KK; jj++) s += __expf(sE[i * 17 + jj] - m);
        sAm[i * 17 + j] = __expf(E - m) / s;
    }
    __syncthreads();
    float mv[KK];
    #pragma unroll
    for (int jj = 0; jj < KK; jj++)
        mv[jj] = g_M[(size_t)(b * KK + jj) * DN + d];
    #pragma unroll
    for (int ii = 0; ii < KK; ii++) {
        const float* arow = sAm + ii * 17;
        float acc = 0.f;
        #pragma unroll
        for (int jj = 0; jj < KK; jj++) acc += arow[jj] * mv[jj];
        int row = b * KK + ii;
        float nv = g_V[(size_t)row * DN + d] + fmaxf(acc, 0.f);
        g_V[(size_t)row * DN + d] = nv;
        ((__half*)g_Abf2)[(size_t)row * KH + d] = __float2half_rn(nv);
        if (outV) outV[(size_t)row * DN + d] = nv;
    }
}

// ---------------- host ----------------------------------------------------
extern "C" void kernel_launch(void* const* d_in, const int* in_sizes, int n_in,
                              void* d_out, int out_size) {
    const float* w    = (const float*)d_in[0];
    const int*   mask = (const int*)  d_in[1];
    const float* nq   = (const float*)d_in[2];
    const float* Wq   = (const float*)d_in[3];
    const float* bq   = (const float*)d_in[4];
    const float* Wk   = (const float*)d_in[5];
    const float* bk   = (const float*)d_in[6];
    const float* Wv   = (const float*)d_in[7];
    const float* bv   = (const float*)d_in[8];
    const float* We1  = (const float*)d_in[9];
    const float* be1  = (const float*)d_in[10];
    const float* We2  = (const float*)d_in[11];
    const float* be2  = (const float*)d_in[12];
    const float* fg   = (const float*)d_in[13];
    const float* Wg   = (const float*)d_in[14];
    const float* bg   = (const float*)d_in[15];

    float* outS = (float*)d_out;
    float* outV = outS + (size_t)BB * NN * KK;
    float* outE = outV + (size_t)BB * KK * DN;

    kPrep<<<PREP_WH + PREP_SPLIT + PREP_KQ, 256>>>(w, Wv, Wg, We1, nq, Wq);
    kQr<<<48, 256>>>(bq);
    kP<<<96, 256>>>(Wk, bk);                                   // g_Pth fp16 + c
    kScoreG<<<308, 128>>>();                                   // scores via HMMA, 64-row tiles
    kU<<<dim3(BB, 4), 96>>>(mask, outS);                       // softmax + fp16 U

    kTGemm<<<dim3(32, 6), 256>>>(0, 0, 1, bv, nq, fg);         // V = U@Wv; fp16 V -> Abf2
    kTGemm<<<dim3(32, 14), 256>>>(1, 0, 3, bg, nullptr, nullptr);   // H = V@We1 AND M = V@Wg0+bg0
    kEdgeP<<<dim3(BB, 2), 256>>>(be1, We2);                    // partial E
    kMsg<<<dim3(BB, 3), 256>>>(be2, nullptr);                  // A inline; V += relu(A@M)
    kTGemm<<<dim3(32, 6), 256>>>(1, 2, 2, bg + DN, nullptr, nullptr); // M = V@Wg1+bg1
    kMsg<<<dim3(BB, 3), 256>>>(be2, outV);                     // final V; Abf2; outV
    kTGemm<<<dim3(32, 8), 256>>>(1, 3, 0, nullptr, nullptr, nullptr); // H on final V
    kEdgeP<<<dim3(BB, 2), 256>>>(be1, We2);                    // partial E (final V)
    kEdgeR<<<BB, 256>>>(be2, outE);                            // E -> out
}

// round 17
// speedup vs baseline: 1.0183x; 1.0002x over previous
#include <cuda_runtime.h>
#include <cuda_bf16.h>
#include <cuda_fp16.h>
#include <math.h>
#include <stdint.h>

// Problem dims
#define BB 256
#define NN 77
#define DD 768
#define KK 16
#define DN 768
#define HID 512
#define MTOT (BB*KK)          // 4096
#define SCALE 0.10206207261596575f   // (768/8)^-0.5
#define KH 768                // GEMM K (fp16)
#define KCH 24                // 768/32 chunks
#define MSC (BB*NN)           // 19712 score rows = 308*64

// ---------------- scratch (device globals; no allocation) ----------------
__device__ float g_Qp[16][KK*DN];
__device__ float g_Q[KK*DN];
__device__ float g_c[KK];
__device__ float g_Sc[(size_t)MSC*KK];   // raw scores [m][k]
__device__ float g_Ep[2][BB*256];        // partial edge logits
__device__ float g_V[MTOT*DN];
__device__ float g_rowsum[MTOT];
__device__ float g_H[MTOT*2*HID];
__device__ float g_M[MTOT*DN];
// fp16 operand buffers (uint4 for 16B alignment)
__device__ uint4 g_wh [(size_t)MSC*DD/8];     // fp16 copy of w
__device__ uint4 g_Pth[KK*DN/8];              // fp16 P, node-major [16][768]
__device__ uint4 g_Abf [(size_t)MTOT*KH/8];   // fp16 U
__device__ uint4 g_Abf2[(size_t)MTOT*KH/8];   // fp16 V
__device__ uint4 g_WbfV [768*KH/8];
__device__ uint4 g_WbfG0[768*KH/8];
__device__ uint4 g_WbfG1[768*KH/8];
__device__ uint4 g_WbfE1[1024*KH/8];

__device__ __forceinline__ uint32_t smem_u32(const void* p) {
    uint32_t a;
    asm("{ .reg .u64 t; cvta.to.shared.u64 t, %1; cvt.u32.u64 %0, t; }"
        : "=r"(a) : "l"(p));
    return a;
}

__device__ __forceinline__ unsigned packh2(float a, float b) {
    __half2 h = __floats2half2_rn(a, b);
    return *(unsigned*)&h;
}

// ---------------- kPrep: fused w->fp16, weight conversions, kQ partials ---
#define PREP_WH 7392
#define PREP_SPLIT 1248
#define PREP_KQ 48
__global__ void kPrep(const float* __restrict__ w,
                      const float* __restrict__ Wv,
                      const float* __restrict__ Wg,
                      const float* __restrict__ We1,
                      const float* __restrict__ nq,
                      const float* __restrict__ Wq) {
    int bid = blockIdx.x;
    int tid = threadIdx.x;
    if (bid < PREP_WH) {
        size_t idx = (size_t)bid * 256 + tid;
        const float4* s = (const float4*)w + idx * 2;
        float4 a = s[0], b = s[1];
        uint4 o;
        o.x = packh2(a.x, a.y); o.y = packh2(a.z, a.w);
        o.z = packh2(b.x, b.y); o.w = packh2(b.z, b.w);
        g_wh[idx] = o;
    } else if (bid < PREP_WH + PREP_SPLIT) {
        int sid = (bid - PREP_WH) * 256 + tid;
        float a[8];
        __half* out;
        int e0;
        if (sid < 221184) {
            int job = sid / 73728, s = sid % 73728;
            int n = s % 768, seg = s / 768;
            e0 = seg * 8;
            const float* Wp = (job == 0) ? Wv : (job == 1) ? Wg : (Wg + 768 * 768);
            uint4* o4 = (job == 0) ? g_WbfV : (job == 1) ? g_WbfG0 : g_WbfG1;
            out = (__half*)o4 + (size_t)n * KH;
            #pragma unroll
            for (int i = 0; i < 8; i++) a[i] = Wp[(size_t)(e0 + i) * 768 + n];
        } else {
            int s = sid - 221184;
            int n = s % 1024, seg = s / 1024;
            e0 = seg * 8;
            out = (__half*)g_WbfE1 + (size_t)n * KH;
            size_t base = (n < HID) ? (size_t)n : ((size_t)768 * HID + (n - HID));
            #pragma unroll
            for (int i = 0; i < 8; i++) a[i] = We1[base + (size_t)(e0 + i) * HID];
        }
        unsigned h[4];
        #pragma unroll
        for (int i = 0; i < 4; i++) h[i] = packh2(a[2 * i], a[2 * i + 1]);
        *(uint4*)(out + e0) = *(uint4*)h;
    } else {
        int q = bid - (PREP_WH + PREP_SPLIT);
        int dblk = q % 3, sl = q / 3;
        int d = dblk * 256 + tid;
        int e0 = sl * 48;
        __shared__ float snq[KK][48];
        for (int idx = tid; idx < KK * 48; idx += 256)
            snq[idx / 48][idx % 48] = nq[(idx / 48) * DN + e0 + idx % 48];
        __syncthreads();
        float acc[KK];
        #pragma unroll
        for (int k = 0; k < KK; k++) acc[k] = 0.f;
        const float* wp = Wq + (size_t)e0 * DN + d;
        #pragma unroll 4
        for (int e = 0; e < 48; e++) {
            float wv = wp[(size_t)e * DN];
            #pragma unroll
            for (int k = 0; k < KK; k++) acc[k] += snq[k][e] * wv;
        }
        #pragma unroll
        for (int k = 0; k < KK; k++) g_Qp[sl][k * DN + d] = acc[k];
    }
}

// ---------------- kQr: sum 16 partials + bq -> g_Q ------------------------
__global__ void kQr(const float* __restrict__ bq) {
    int i = blockIdx.x * 256 + threadIdx.x;   // 12288
    float s = bq[i % DN];
    #pragma unroll
    for (int sl = 0; sl < 16; sl++) s += g_Qp[sl][i];
    g_Q[i] = s;
}

// ---------------- kP: P -> fp16 g_Pth directly; c[k] ----------------------
__global__ void kP(const float* __restrict__ Wk, const float* __restrict__ bk) {
    __shared__ float sQ[KK][DN];   // 48 KB
    __shared__ float sPo[8][17];
    int tid = threadIdx.x;
    int lane = tid & 31, warp = tid >> 5;
    for (int idx = tid; idx < KK * DN; idx += 256)
        sQ[idx / DN][idx % DN] = g_Q[idx];
    __syncthreads();

    int j = blockIdx.x * 8 + warp;
    const float4* wr = (const float4*)(Wk + (size_t)j * DN);
    float acc[KK];
    #pragma unroll
    for (int k = 0; k < KK; k++) acc[k] = 0.f;
    #pragma unroll
    for (int it = 0; it < 6; it++) {
        int e = it * 128 + lane * 4;
        float4 wv = wr[it * 32 + lane];
        #pragma unroll
        for (int k = 0; k < KK; k++) {
            float4 qv = *(const float4*)&sQ[k][e];
            acc[k] += wv.x * qv.x + wv.y * qv.y + wv.z * qv.z + wv.w * qv.w;
        }
    }
    float out = 0.f;
    #pragma unroll
    for (int k = 0; k < KK; k++) {
        float v = acc[k];
        v += __shfl_xor_sync(0xFFFFFFFFu, v, 16);
        v += __shfl_xor_sync(0xFFFFFFFFu, v, 8);
        v += __shfl_xor_sync(0xFFFFFFFFu, v, 4);
        v += __shfl_xor_sync(0xFFFFFFFFu, v, 2);
        v += __shfl_xor_sync(0xFFFFFFFFu, v, 1);
        if (lane == k) out = v;
    }
    if (lane < KK) sPo[warp][lane] = out;   // sPo[jj][k]
    __syncthreads();
    if (tid < 128) {
        int k = tid >> 3, jj = tid & 7;
        ((__half*)g_Pth)[k * DN + blockIdx.x * 8 + jj] = __float2half_rn(sPo[jj][k]);
    }

    if (blockIdx.x >= 94) {
        int k = (blockIdx.x - 94) * 8 + warp;
        float cc = 0.f;
        #pragma unroll
        for (int it = 0; it < 6; it++) {
            int e = it * 128 + lane * 4;
            float4 bv = *(const float4*)(bk + e);
            float4 qv = *(const float4*)&sQ[k][e];
            cc += bv.x * qv.x + bv.y * qv.y + bv.z * qv.z + bv.w * qv.w;
        }
        cc += __shfl_xor_sync(0xFFFFFFFFu, cc, 16);
        cc += __shfl_xor_sync(0xFFFFFFFFu, cc, 8);
        cc += __shfl_xor_sync(0xFFFFFFFFu, cc, 4);
        cc += __shfl_xor_sync(0xFFFFFFFFu, cc, 2);
        cc += __shfl_xor_sync(0xFFFFFFFFu, cc, 1);
        if (lane == 0) g_c[k] = cc;
    }
}

// ---------------- kScoreG: scores = wh @ Pth^T, 64-row tiles --------------
// grid 308, block 128 (4 warps); cp.async SIX-stage A pipeline
#define SC_STAGES 6
__global__ __launch_bounds__(128) void kScoreG() {
    __shared__ __align__(1024) __half sB[16 * 768];           // 24 KB
    __shared__ __align__(1024) __half sA[SC_STAGES][64 * 32]; // 24 KB

    const __half* Ag = (const __half*)g_wh;
    const int m0 = blockIdx.x * 64;
    const int tid = threadIdx.x;
    const int lane = tid & 31, warp = tid >> 5;
    const uint32_t sAu = smem_u32(sA), sBu = smem_u32(sB);

    // load B (16 nodes x 768 fp16) with unit-XOR swizzle
    for (int idx = tid; idx < 16 * 96; idx += 128) {
        int r = idx / 96, u = idx % 96;
        uint4 v = g_Pth[r * 96 + u];
        *(uint4*)((char*)sB + r * 1536 + ((u ^ (r & 7)) << 4)) = v;
    }

    // A staging slots: 2 x 16B per thread per chunk (64 rows x 4 quads)
    uint32_t soff[2];
    const __half* gA[2];
    #pragma unroll
    for (int i = 0; i < 2; i++) {
        int v = tid * 2 + i, row = v >> 2, q = v & 3;
        soff[i] = row * 64 + ((q ^ ((row >> 1) & 3)) << 4);
        gA[i] = Ag + (size_t)(m0 + row) * KH + q * 8;
    }

    const int r16 = lane & 15, hh = lane >> 4;
    uint32_t aoff[2];
    #pragma unroll
    for (int s = 0; s < 2; s++) {
        int quad = 2 * s + hh;
        int row = warp * 16 + r16;
        aoff[s] = row * 64 + ((quad ^ ((row >> 1) & 3)) << 4);
    }

    float acc[2][4];
    #pragma unroll
    for (int b = 0; b < 2; b++)
        #pragma unroll
        for (int r = 0; r < 4; r++) acc[b][r] = 0.f;

    #pragma unroll
    for (int st = 0; st < SC_STAGES - 1; st++) {
        uint32_t da = sAu + st * 4096;
        #pragma unroll
        for (int i = 0; i < 2; i++)
            asm volatile("cp.async.ca.shared.global [%0], [%1], 16;"
                         :: "r"(da + soff[i]), "l"(gA[i] + st * 32));
        asm volatile("cp.async.commit_group;");
    }
    __syncthreads();   // B visible

    for (int c = 0; c < KCH; c++) {
        const int buf = c % SC_STAGES;
        if (c + SC_STAGES - 1 < KCH + SC_STAGES - 1) {
            if (c + SC_STAGES - 1 < KCH || true) {
                // wait so that stage `buf` is complete:
            }
        }
        if (c + SC_STAGES - 2 < KCH) asm volatile("cp.async.wait_group %0;" :: "n"(SC_STAGES - 2));
        else                          asm volatile("cp.async.wait_group 0;");
        __syncthreads();
        if (c + SC_STAGES - 1 < KCH) {
            const uint32_t da = sAu + ((c + SC_STAGES - 1) % SC_STAGES) * 4096;
            #pragma unroll
            for (int i = 0; i < 2; i++)
                asm volatile("cp.async.ca.shared.global [%0], [%1], 16;"
                             :: "r"(da + soff[i]), "l"(gA[i] + (c + SC_STAGES - 1) * 32));
            asm volatile("cp.async.commit_group;");
        }

        const uint32_t baseA = sAu + buf * 4096;
        #pragma unroll
        for (int s = 0; s < 2; s++) {
            uint32_t afr[4];
            asm volatile("ldmatrix.sync.aligned.m8n8.x4.shared.b16 "
                         "{%0,%1,%2,%3}, [%4];"
                         : "=r"(afr[0]), "=r"(afr[1]), "=r"(afr[2]), "=r"(afr[3])
                         : "r"(baseA + aoff[s]));
            int u = c * 4 + s * 2 + hh;
            uint32_t baddr = sBu + r16 * 1536 + ((u ^ (r16 & 7)) << 4);
            uint32_t r0, r1, r2, r3;
            asm volatile("ldmatrix.sync.aligned.m8n8.x4.shared.b16 "
                         "{%0,%1,%2,%3}, [%4];"
                         : "=r"(r0), "=r"(r1), "=r"(r2), "=r"(r3) : "r"(baddr));
            uint32_t bfr[2][2];
            bfr[0][0] = r0; bfr[0][1] = r2;
            bfr[1][0] = r1; bfr[1][1] = r3;
            #pragma unroll
            for (int nt = 0; nt < 2; nt++) {
                asm volatile(
                    "mma.sync.aligned.m16n8k16.row.col.f32.f16.f16.f32 "
                    "{%0,%1,%2,%3}, {%4,%5,%6,%7}, {%8,%9}, {%0,%1,%2,%3};"
                    : "+f"(acc[nt][0]), "+f"(acc[nt][1]),
                      "+f"(acc[nt][2]), "+f"(acc[nt][3])
                    : "r"(afr[0]), "r"(afr[1]), "r"(afr[2]), "r"(afr[3]),
                      "r"(bfr[nt][0]), "r"(bfr[nt][1]));
            }
        }
    }

    #pragma unroll
    for (int half = 0; half < 2; half++) {
        int row = m0 + warp * 16 + (lane >> 2) + 8 * half;
        float* crow = g_Sc + (size_t)row * KK;
        #pragma unroll
        for (int nt = 0; nt < 2; nt++) {
            int col = nt * 8 + (lane & 3) * 2;
            crow[col]     = acc[nt][half * 2 + 0];
            crow[col + 1] = acc[nt][half * 2 + 1];
        }
    }
}

// ---------------- kU: softmax (from g_Sc) + U = S^T w, fp16 U out ---------
__global__ void kU(const int* __restrict__ mask, float* __restrict__ outS) {
    int b = blockIdx.x, dh = blockIdx.y;
    int tid = threadIdx.x;
    int d0 = dh * 192 + tid * 2;
    __shared__ float sS[NN * KK];
    __shared__ float sC[KK];
    if (tid < KK) sC[tid] = g_c[tid];
    __syncthreads();
    if (tid < NN) {
        int n = tid;
        float v[KK];
        const float4* src = (const float4*)(g_Sc + (size_t)(b * NN + n) * KK);
        #pragma unroll
        for (int q = 0; q < 4; q++) *(float4*)&v[q * 4] = src[q];
        if (mask[b * NN + n] == 0) {
            #pragma unroll
            for (int k = 0; k < KK; k++) sS[n * KK + k] = 1.0f / 16.0f;
        } else {
            float sc[KK]; float m = -3.4e38f;
            #pragma unroll
            for (int k = 0; k < KK; k++) { sc[k] = (v[k] + sC[k]) * SCALE; m = fmaxf(m, sc[k]); }
            float e[KK]; float s = 0.f;
            #pragma unroll
            for (int k = 0; k < KK; k++) { e[k] = __expf(sc[k] - m); s += e[k]; }
            float inv = 1.0f / s;
            #pragma unroll
            for (int k = 0; k < KK; k++) sS[n * KK + k] = e[k] * inv;
        }
        if (dh == 0) {
            float4* dst = (float4*)(outS + (size_t)(b * NN + n) * KK);
            #pragma unroll
            for (int q = 0; q < 4; q++) dst[q] = *(float4*)&sS[n * KK + q * 4];
        }
    }
    __syncthreads();
    if (dh == 0 && tid < KK) {
        float s = 0.f;
        for (int n = 0; n < NN; n++) s += sS[n * KK + tid];
        g_rowsum[b * KK + tid] = s;
    }

    float2 acc[KK];
    #pragma unroll
    for (int k = 0; k < KK; k++) { acc[k].x = 0.f; acc[k].y = 0.f; }
    const __half* wp = (const __half*)g_wh + (size_t)b * NN * DD + d0;
    #pragma unroll 4
    for (int n = 0; n < NN; n++) {
        __half2 hv = *(const __half2*)(wp + (size_t)n * DD);
        float2 wv = __half22float2(hv);
        const float* srow = sS + n * KK;
        #pragma unroll
        for (int k = 0; k < KK; k++) {
            float s = srow[k];
            acc[k].x += s * wv.x; acc[k].y += s * wv.y;
        }
    }
    #pragma unroll
    for (int k = 0; k < KK; k++) {
        __half* ur = (__half*)g_Abf + (size_t)(b * KK + k) * KH;
        *(unsigned*)(ur + d0) = packh2(acc[k].x, acc[k].y);
    }
}

// ---------------- kTGemm: mma.sync fp16 GEMM ------------------------------
__global__ __launch_bounds__(256, 2) void kTGemm(
    int asel, int wsel, int mode, const float* __restrict__ bias,
    const float* __restrict__ nq, const float* __restrict__ gatep)
{
    __shared__ __align__(1024) __half sA[3][128 * 32];
    __shared__ __align__(1024) __half sB[3][128 * 32];

    const __half* Ag = (const __half*)(asel ? g_Abf2 : g_Abf);
    const int m0 = blockIdx.x * 128;
    int n0 = blockIdx.y * 128;
    const __half* Bg;
    float* C; int Ncols; int emode = mode;
    if (mode == 3) {
        if (blockIdx.y < 8) {
            Bg = (const __half*)g_WbfE1; C = g_H; Ncols = 2 * HID; emode = 0;
        } else {
            n0 = (blockIdx.y - 8) * 128;
            Bg = (const __half*)g_WbfG0; C = g_M; Ncols = DN; emode = 2;
        }
    } else {
        const uint4* B4 = (wsel == 0) ? g_WbfV : (wsel == 1) ? g_WbfG0
                        : (wsel == 2) ? g_WbfG1 : g_WbfE1;
        Bg = (const __half*)B4;
        if (mode == 0)      { C = g_H; Ncols = 2 * HID; }
        else if (mode == 1) { C = g_V; Ncols = DN; }
        else                { C = g_M; Ncols = DN; }
    }

    const int tid = threadIdx.x;
    const int lane = tid & 31, warp = tid >> 5;
    const int wm = warp >> 1, wn = warp & 1;

    const uint32_t sAu = smem_u32(sA), sBu = smem_u32(sB);

    uint32_t soff[2];
    const __half* gA[2];
    const __half* gB[2];
    #pragma unroll
    for (int i = 0; i < 2; i++) {
        int v = tid * 2 + i, row = v >> 2, q = v & 3;
        soff[i] = row * 64 + ((q ^ ((row >> 1) & 3)) << 4);
        gA[i] = Ag + (size_t)(m0 + row) * KH + q * 8;
        gB[i] = Bg + (size_t)(n0 + row) * KH + q * 8;
    }

    const int r16 = lane & 15, hh = lane >> 4;
    uint32_t aoff[2][2], boff[2][4];
    #pragma unroll
    for (int s = 0; s < 2; s++) {
        int quad = 2 * s + hh;
        #pragma unroll
        for (int mt = 0; mt < 2; mt++) {
            int row = wm * 32 + mt * 16 + r16;
            aoff[s][mt] = row * 64 + ((quad ^ ((row >> 1) & 3)) << 4);
        }
        #pragma unroll
        for (int nb = 0; nb < 4; nb++) {
            int row = wn * 64 + nb * 16 + r16;
            boff[s][nb] = row * 64 + ((quad ^ ((row >> 1) & 3)) << 4);
        }
    }

    float acc[2][8][4];
    #pragma unroll
    for (int a = 0; a < 2; a++)
        #pragma unroll
        for (int b = 0; b < 8; b++)
            #pragma unroll
            for (int r = 0; r < 4; r++) acc[a][b][r] = 0.f;

    #pragma unroll
    for (int st = 0; st < 2; st++) {
        uint32_t da = sAu + st * 8192, db = sBu + st * 8192;
        #pragma unroll
        for (int i = 0; i < 2; i++) {
            asm volatile("cp.async.ca.shared.global [%0], [%1], 16;"
                         :: "r"(da + soff[i]), "l"(gA[i] + st * 32));
            asm volatile("cp.async.ca.shared.global [%0], [%1], 16;"
                         :: "r"(db + soff[i]), "l"(gB[i] + st * 32));
        }
        asm volatile("cp.async.commit_group;");
    }

    for (int c = 0; c < KCH; c++) {
        const int buf = c % 3;
        if (c + 1 < KCH) asm volatile("cp.async.wait_group 1;");
        else             asm volatile("cp.async.wait_group 0;");
        __syncthreads();
        if (c + 2 < KCH) {
            const int wb = (c + 2) % 3;
            const uint32_t da = sAu + wb * 8192, db = sBu + wb * 8192;
            #pragma unroll
            for (int i = 0; i < 2; i++) {
                asm volatile("cp.async.ca.shared.global [%0], [%1], 16;"
                             :: "r"(da + soff[i]), "l"(gA[i] + (c + 2) * 32));
                asm volatile("cp.async.ca.shared.global [%0], [%1], 16;"
                             :: "r"(db + soff[i]), "l"(gB[i] + (c + 2) * 32));
            }
            asm volatile("cp.async.commit_group;");
        }

        const uint32_t baseA = sAu + buf * 8192;
        const uint32_t baseB = sBu + buf * 8192;
        #pragma unroll
        for (int s = 0; s < 2; s++) {
            uint32_t afr[2][4];
            #pragma unroll
            for (int mt = 0; mt < 2; mt++) {
                asm volatile("ldmatrix.sync.aligned.m8n8.x4.shared.b16 "
                             "{%0,%1,%2,%3}, [%4];"
                             : "=r"(afr[mt][0]), "=r"(afr[mt][1]),
                               "=r"(afr[mt][2]), "=r"(afr[mt][3])
                             : "r"(baseA + aoff[s][mt]));
            }
            uint32_t bfr[8][2];
            #pragma unroll
            for (int nb = 0; nb < 4; nb++) {
                uint32_t r0, r1, r2, r3;
                asm volatile("ldmatrix.sync.aligned.m8n8.x4.shared.b16 "
                             "{%0,%1,%2,%3}, [%4];"
                             : "=r"(r0), "=r"(r1), "=r"(r2), "=r"(r3)
                             : "r"(baseB + boff[s][nb]));
                bfr[nb * 2][0] = r0;     bfr[nb * 2][1] = r2;
                bfr[nb * 2 + 1][0] = r1; bfr[nb * 2 + 1][1] = r3;
            }
            #pragma unroll
            for (int mt = 0; mt < 2; mt++)
                #pragma unroll
                for (int nt = 0; nt < 8; nt++) {
                    asm volatile(
                        "mma.sync.aligned.m16n8k16.row.col.f32.f16.f16.f32 "
                        "{%0,%1,%2,%3}, {%4,%5,%6,%7}, {%8,%9}, {%0,%1,%2,%3};"
                        : "+f"(acc[mt][nt][0]), "+f"(acc[mt][nt][1]),
                          "+f"(acc[mt][nt][2]), "+f"(acc[mt][nt][3])
                        : "r"(afr[mt][0]), "r"(afr[mt][1]),
                          "r"(afr[mt][2]), "r"(afr[mt][3]),
                          "r"(bfr[nt][0]), "r"(bfr[nt][1]));
                }
        }
    }

    float gate = 0.f, omg = 1.f;
    if (emode == 1) {
        gate = 1.0f / (1.0f + expf(-gatep[0]));
        omg = 1.0f - gate;
    }
    #pragma unroll
    for (int mt = 0; mt < 2; mt++) {
        #pragma unroll
        for (int half = 0; half < 2; half++) {
            int row = m0 + wm * 32 + mt * 16 + (lane >> 2) + 8 * half;
            float rsv = 0.f; const float* nqr = nullptr;
            __half* arow2 = nullptr;
            if (emode == 1) {
                rsv = g_rowsum[row];
                nqr = nq + (size_t)(row & 15) * DN;
                arow2 = (__half*)g_Abf2 + (size_t)row * KH;
            }
            float* crow = C + (size_t)row * Ncols;
            #pragma unroll
            for (int nt = 0; nt < 8; nt++) {
                int col = n0 + wn * 64 + nt * 8 + (lane & 3) * 2;
                float v0 = acc[mt][nt][half * 2 + 0];
                float v1 = acc[mt][nt][half * 2 + 1];
                if (emode == 1) {
                    v0 += rsv * __ldg(&bias[col]);
                    v1 += rsv * __ldg(&bias[col + 1]);
                    v0 = omg * v0 + gate * __ldg(&nqr[col]);
                    v1 = omg * v1 + gate * __ldg(&nqr[col + 1]);
                    *(unsigned*)(arow2 + col) = packh2(v0, v1);
                } else if (emode == 2) {
                    v0 += __ldg(&bias[col]);
                    v1 += __ldg(&bias[col + 1]);
                }
                float2 o; o.x = v0; o.y = v1;
                *(float2*)(crow + col) = o;
            }
        }
    }
}

// ---------------- kEdgeP: partial edge logits, float4 inner ---------------
__global__ void kEdgeP(const float* __restrict__ be1, const float* __restrict__ We2) {
    int b = blockIdx.x;
    int h0 = blockIdx.y * 256;
    int tid = threadIdx.x;
    int i = tid >> 4, j = tid & 15;
    __shared__ __align__(16) float sHi[KK * 260];
    __shared__ __align__(16) float sHj[KK * 260];
    __shared__ __align__(16) float sW2[256];

    for (int idx = tid; idx < KK * 256; idx += 256) {
        int r = idx >> 8, c = idx & 255;
        sHi[r * 260 + c] = g_H[(size_t)(b * KK + r) * (2 * HID) + h0 + c] + be1[h0 + c];
        sHj[r * 260 + c] = g_H[(size_t)(b * KK + r) * (2 * HID) + HID + h0 + c];
    }
    sW2[tid] = We2[h0 + tid];
    __syncthreads();
    const float* hi = sHi + i * 260;
    const float* hj = sHj + j * 260;
    float a0 = 0.f, a1 = 0.f, a2 = 0.f, a3 = 0.f;
    #pragma unroll 4
    for (int c = 0; c < 256; c += 4) {
        float4 h4 = *(const float4*)&hi[c];
        float4 g4 = *(const float4*)&hj[c];
        float4 w4 = *(const float4*)&sW2[c];
        a0 += fmaxf(h4.x + g4.x, 0.f) * w4.x;
        a1 += fmaxf(h4.y + g4.y, 0.f) * w4.y;
        a2 += fmaxf(h4.z + g4.z, 0.f) * w4.z;
        a3 += fmaxf(h4.w + g4.w, 0.f) * w4.w;
    }
    g_Ep[blockIdx.y][b * 256 + tid] = (a0 + a1) + (a2 + a3);
}

// ---------------- kEdgeR: combine partials -> outE ------------------------
__global__ void kEdgeR(const float* __restrict__ be2, float* __restrict__ outE) {
    int b = blockIdx.x;
    int tid = threadIdx.x;
    outE[b * 256 + tid] = g_Ep[0][b * 256 + tid] + g_Ep[1][b * 256 + tid] + be2[0];
}

// ---------------- kMsg: A-softmax from g_Ep, V += relu(A@M), fp16 V -------
__global__ void kMsg(const float* __restrict__ be2, float* __restrict__ outV) {
    int b = blockIdx.x, dh = blockIdx.y;
    int tid = threadIdx.x;
    int d = dh * 256 + tid;
    __shared__ float sE[KK * 17];
    __shared__ float sAm[KK * 17];
    int i = tid >> 4, j = tid & 15;
    float E = g_Ep[0][b * 256 + tid] + g_Ep[1][b * 256 + tid] + be2[0];
    sE[i * 17 + j] = E;
    __syncthreads();
    {
        float m = -3.4e38f;
        #pragma unroll
        for (int jj = 0; jj < KK; jj++) m = fmaxf(m, sE[i * 17 + jj]);
        float s = 0.f;
        #pragma unroll
        for (int jj = 0; jj < KK; jj++) s += __expf(sE[i * 17 + jj] - m);
        sAm[i * 17 + j] = __expf(E - m) / s;
    }
    __syncthreads();
    float mv[KK];
    #pragma unroll
    for (int jj = 0; jj < KK; jj++)
        mv[jj] = g_M[(size_t)(b * KK + jj) * DN + d];
    #pragma unroll
    for (int ii = 0; ii < KK; ii++) {
        const float* arow = sAm + ii * 17;
        float acc = 0.f;
        #pragma unroll
        for (int jj = 0; jj < KK; jj++) acc += arow[jj] * mv[jj];
        int row = b * KK + ii;
        float nv = g_V[(size_t)row * DN + d] + fmaxf(acc, 0.f);
        g_V[(size_t)row * DN + d] = nv;
        ((__half*)g_Abf2)[(size_t)row * KH + d] = __float2half_rn(nv);
        if (outV) outV[(size_t)row * DN + d] = nv;
    }
}

// ---------------- host ----------------------------------------------------
extern "C" void kernel_launch(void* const* d_in, const int* in_sizes, int n_in,
                              void* d_out, int out_size) {
    const float* w    = (const float*)d_in[0];
    const int*   mask = (const int*)  d_in[1];
    const float* nq   = (const float*)d_in[2];
    const float* Wq   = (const float*)d_in[3];
    const float* bq   = (const float*)d_in[4];
    const float* Wk   = (const float*)d_in[5];
    const float* bk   = (const float*)d_in[6];
    const float* Wv   = (const float*)d_in[7];
    const float* bv   = (const float*)d_in[8];
    const float* We1  = (const float*)d_in[9];
    const float* be1  = (const float*)d_in[10];
    const float* We2  = (const float*)d_in[11];
    const float* be2  = (const float*)d_in[12];
    const float* fg   = (const float*)d_in[13];
    const float* Wg   = (const float*)d_in[14];
    const float* bg   = (const float*)d_in[15];

    float* outS = (float*)d_out;
    float* outV = outS + (size_t)BB * NN * KK;
    float* outE = outV + (size_t)BB * KK * DN;

    kPrep<<<PREP_WH + PREP_SPLIT + PREP_KQ, 256>>>(w, Wv, Wg, We1, nq, Wq);
    kQr<<<48, 256>>>(bq);
    kP<<<96, 256>>>(Wk, bk);                                   // g_Pth fp16 + c
    kScoreG<<<308, 128>>>();                                   // scores via HMMA, 6-stage
    kU<<<dim3(BB, 4), 96>>>(mask, outS);                       // softmax + fp16 U

    kTGemm<<<dim3(32, 6), 256>>>(0, 0, 1, bv, nq, fg);         // V = U@Wv; fp16 V -> Abf2
    kTGemm<<<dim3(32, 14), 256>>>(1, 0, 3, bg, nullptr, nullptr);   // H = V@We1 AND M = V@Wg0+bg0
    kEdgeP<<<dim3(BB, 2), 256>>>(be1, We2);                    // partial E
    kMsg<<<dim3(BB, 3), 256>>>(be2, nullptr);                  // A inline; V += relu(A@M)
    kTGemm<<<dim3(32, 6), 256>>>(1, 2, 2, bg + DN, nullptr, nullptr); // M = V@Wg1+bg1
    kMsg<<<dim3(BB, 3), 256>>>(be2, outV);                     // final V; Abf2; outV
    kTGemm<<<dim3(32, 8), 256>>>(1, 3, 0, nullptr, nullptr, nullptr); // H on final V
    kEdgeP<<<dim3(BB, 2), 256>>>(be1, We2);                    // partial E (final V)
    kEdgeR<<<BB, 256>>>(be2, outE);                            // E -> out
}